// round 14
// baseline (speedup 1.0000x reference)
#include <cuda_runtime.h>
#include <cstdint>

// out[i] = sum_j relu(adj[i,j] * Linv[i,j]) * W[j] + b
// N = 8192. Inputs: d_in[0]=x_e (unused), d_in[1]=Linv, d_in[2]=adjacency,
// d_in[3]=W (N floats), d_in[4]=b (1 float). Output: N floats ([N,1]).
//
// TMA data path experiment: each half-row CTA pulls its 2x16KB input via two
// cp.async.bulk transfers (whole input posted at once -> max DRAM MLP, no
// per-thread LDG path), computes from smem, and combines halves with the
// proven acq_rel flag tail (single launch, deterministic p0+p1+b).

#define N_DIM 8192
#define THREADS 256
#define HALF_F4 (N_DIM / 4 / 2)          // 1024 float4 per half-row
#define HALF_BYTES (HALF_F4 * 16)        // 16384 bytes per stream

__device__ float g_partials[2 * N_DIM];
__device__ int   g_flags[N_DIM];         // zero-init; reset after each use

__device__ __forceinline__ uint32_t smem_u32(const void* p) {
    uint32_t a;
    asm("{ .reg .u64 t; cvta.to.shared.u64 t, %1; cvt.u32.u64 %0, t; }"
        : "=r"(a) : "l"(p));
    return a;
}

__device__ __forceinline__ void mbar_wait_parity(uint32_t mbar, uint32_t parity) {
    asm volatile(
        "{\n\t"
        ".reg .pred P;\n\t"
        "W%=:\n\t"
        "mbarrier.try_wait.parity.shared::cta.b64 P, [%0], %1;\n\t"
        "@!P bra W%=;\n\t"
        "}" :: "r"(mbar), "r"(parity) : "memory");
}

__global__ __launch_bounds__(THREADS)
void dist2cycle_tma_halfrow_kernel(const float4* __restrict__ Linv,
                                   const float4* __restrict__ adj,
                                   const float4* __restrict__ W4,
                                   const float*  __restrict__ bptr,
                                   float* __restrict__ out) {
    __shared__ alignas(128) float4 sL[HALF_F4];   // 16 KB
    __shared__ alignas(128) float4 sA[HALF_F4];   // 16 KB
    __shared__ alignas(8)   uint64_t mbar;
    __shared__ float warp_sums[THREADS / 32];

    const int row  = blockIdx.x >> 1;
    const int half = blockIdx.x & 1;
    const size_t base = (size_t)row * (N_DIM / 4) + (size_t)half * HALF_F4;

    const uint32_t mb = smem_u32(&mbar);

    if (threadIdx.x == 0) {
        asm volatile("mbarrier.init.shared.b64 [%0], 1;" :: "r"(mb) : "memory");
    }
    __syncthreads();   // init visible to all before anyone waits

    if (threadIdx.x == 0) {
        asm volatile("mbarrier.arrive.expect_tx.shared.b64 _, [%0], %1;"
                     :: "r"(mb), "r"(2u * HALF_BYTES) : "memory");
        const uint32_t dL = smem_u32(sL);
        const uint32_t dA = smem_u32(sA);
        asm volatile(
            "cp.async.bulk.shared::cta.global.mbarrier::complete_tx::bytes "
            "[%0], [%1], %2, [%3];"
            :: "r"(dL), "l"(Linv + base), "r"((uint32_t)HALF_BYTES), "r"(mb)
            : "memory");
        asm volatile(
            "cp.async.bulk.shared::cta.global.mbarrier::complete_tx::bytes "
            "[%0], [%1], %2, [%3];"
            :: "r"(dA), "l"(adj + base), "r"((uint32_t)HALF_BYTES), "r"(mb)
            : "memory");
    }

    mbar_wait_parity(mb, 0);

    const float4* __restrict__ Wh = W4 + (size_t)half * HALF_F4;
    float acc = 0.0f;

    // 1024 float4 over 256 threads -> 4 iterations, conflict-free LDS.128.
    #pragma unroll 4
    for (int j = threadIdx.x; j < HALF_F4; j += THREADS) {
        float4 l = sL[j];
        float4 a = sA[j];
        float4 w = __ldg(&Wh[j]);
        acc = fmaf(fmaxf(a.x * l.x, 0.0f), w.x, acc);
        acc = fmaf(fmaxf(a.y * l.y, 0.0f), w.y, acc);
        acc = fmaf(fmaxf(a.z * l.z, 0.0f), w.z, acc);
        acc = fmaf(fmaxf(a.w * l.w, 0.0f), w.w, acc);
    }

    // Warp reduce
    #pragma unroll
    for (int off = 16; off > 0; off >>= 1)
        acc += __shfl_xor_sync(0xFFFFFFFFu, acc, off);

    const int lane = threadIdx.x & 31;
    const int wid  = threadIdx.x >> 5;
    if (lane == 0) warp_sums[wid] = acc;
    __syncthreads();

    if (wid == 0) {
        float v = (lane < THREADS / 32) ? warp_sums[lane] : 0.0f;
        #pragma unroll
        for (int off = 4; off > 0; off >>= 1)
            v += __shfl_xor_sync(0xFFFFFFFFu, v, off);

        if (lane == 0) {
            __stcg(&g_partials[2 * row + half], v);
            int prev;
            asm volatile("atom.add.acq_rel.gpu.global.s32 %0, [%1], 1;"
                         : "=r"(prev) : "l"(&g_flags[row]) : "memory");
            if (prev == 1) {
                float p0 = __ldcg(&g_partials[2 * row + 0]);
                float p1 = __ldcg(&g_partials[2 * row + 1]);
                out[row] = p0 + p1 + __ldg(bptr);
                g_flags[row] = 0;   // clean state for next graph replay
            }
        }
    }
}

extern "C" void kernel_launch(void* const* d_in, const int* in_sizes, int n_in,
                              void* d_out, int out_size) {
    // metadata order: x_e, Linv, adjacency, W, b
    const float4* Linv = (const float4*)d_in[1];
    const float4* adj  = (const float4*)d_in[2];
    const float4* W4   = (const float4*)d_in[3];
    const float*  b    = (const float*)d_in[4];
    float* out = (float*)d_out;

    dist2cycle_tma_halfrow_kernel<<<2 * N_DIM, THREADS>>>(Linv, adj, W4, b, out);
}

// round 15
// speedup vs baseline: 1.1825x; 1.1825x over previous
#include <cuda_runtime.h>
#include <cstdint>

// out[i] = sum_j relu(adj[i,j] * Linv[i,j]) * W[j] + b
// N = 8192. Inputs: d_in[0]=x_e (unused), d_in[1]=Linv, d_in[2]=adjacency,
// d_in[3]=W (N floats), d_in[4]=b (1 float). Output: N floats ([N,1]).
//
// Stage 1 (16384 CTAs, one per half-row): pure streaming reduce, partial
// published with a plain __stcg. Lane 0 then signals
// griddepcontrol.launch_dependents — AFTER the store, so the PDL contract
// makes all partials visible to the dependent grid once it launches (the
// dependent launches only when every primary CTA has signaled/exited).
// Stage 2 (PDL combiner): griddepcontrol.wait, then out[i] = p0 + p1 + b.
// No atomics, no flags, no spin, no resets -> deterministic and replay-clean.

#define N_DIM 8192
#define THREADS 256
#define HALF_F4 (N_DIM / 4 / 2)   // 1024 float4 per half-row

__device__ float g_partials[2 * N_DIM];

__global__ __launch_bounds__(THREADS, 8)
void dist2cycle_halfrow_pdl_kernel(const float4* __restrict__ Linv,
                                   const float4* __restrict__ adj,
                                   const float4* __restrict__ W4) {
    const int row  = blockIdx.x >> 1;
    const int half = blockIdx.x & 1;

    const size_t base = (size_t)row * (N_DIM / 4) + (size_t)half * HALF_F4;
    const float4* __restrict__ L = Linv + base;
    const float4* __restrict__ A = adj  + base;
    const float4* __restrict__ W = W4 + (size_t)half * HALF_F4;

    float acc = 0.0f;

    // 1024 float4 over 256 threads -> 4 iterations.
    #pragma unroll 4
    for (int j = threadIdx.x; j < HALF_F4; j += THREADS) {
        float4 l = __ldcs(&L[j]);
        float4 a = __ldcs(&A[j]);
        float4 w = __ldg(&W[j]);
        acc = fmaf(fmaxf(a.x * l.x, 0.0f), w.x, acc);
        acc = fmaf(fmaxf(a.y * l.y, 0.0f), w.y, acc);
        acc = fmaf(fmaxf(a.z * l.z, 0.0f), w.z, acc);
        acc = fmaf(fmaxf(a.w * l.w, 0.0f), w.w, acc);
    }

    // Warp reduce
    #pragma unroll
    for (int off = 16; off > 0; off >>= 1)
        acc += __shfl_xor_sync(0xFFFFFFFFu, acc, off);

    // Block reduce across 8 warps
    __shared__ float warp_sums[THREADS / 32];
    const int lane = threadIdx.x & 31;
    const int wid  = threadIdx.x >> 5;
    if (lane == 0) warp_sums[wid] = acc;
    __syncthreads();

    if (wid == 0) {
        float v = (lane < THREADS / 32) ? warp_sums[lane] : 0.0f;
        #pragma unroll
        for (int off = 4; off > 0; off >>= 1)
            v += __shfl_xor_sync(0xFFFFFFFFu, v, off);

        if (lane == 0) {
            // Publish partial (L2), THEN signal: the dependent grid only
            // launches once every CTA has signaled, and PDL guarantees
            // pre-signal memory ops are visible to a waiting dependent.
            __stcg(&g_partials[2 * row + half], v);
            asm volatile("griddepcontrol.launch_dependents;");
        }
    }
}

__global__ __launch_bounds__(256)
void dist2cycle_pdl_combine2_kernel(const float* __restrict__ bptr,
                                    float* __restrict__ out) {
    // Block until the primary grid's signaled memory is visible.
    asm volatile("griddepcontrol.wait;");

    const int i = blockIdx.x * blockDim.x + threadIdx.x;
    const float p0 = __ldcg(&g_partials[2 * i + 0]);
    const float p1 = __ldcg(&g_partials[2 * i + 1]);
    out[i] = p0 + p1 + __ldg(bptr);
}

extern "C" void kernel_launch(void* const* d_in, const int* in_sizes, int n_in,
                              void* d_out, int out_size) {
    // metadata order: x_e, Linv, adjacency, W, b
    const float4* Linv = (const float4*)d_in[1];
    const float4* adj  = (const float4*)d_in[2];
    const float4* W4   = (const float4*)d_in[3];
    const float*  b    = (const float*)d_in[4];
    float* out = (float*)d_out;

    dist2cycle_halfrow_pdl_kernel<<<2 * N_DIM, THREADS>>>(Linv, adj, W4);

    cudaLaunchConfig_t cfg = {};
    cfg.gridDim  = dim3(N_DIM / 256, 1, 1);
    cfg.blockDim = dim3(256, 1, 1);
    cfg.dynamicSmemBytes = 0;
    cfg.stream = 0;
    cudaLaunchAttribute attr[1];
    attr[0].id = cudaLaunchAttributeProgrammaticStreamSerialization;
    attr[0].val.programmaticStreamSerializationAllowed = 1;
    cfg.attrs = attr;
    cfg.numAttrs = 1;
    cudaLaunchKernelEx(&cfg, dist2cycle_pdl_combine2_kernel, b, out);
}